// round 5
// baseline (speedup 1.0000x reference)
#include <cuda_runtime.h>
#include <cuda_bf16.h>
#include <math.h>

// Problem constants
#define Bq    4
#define CH_G  64
#define Hh    240
#define Ww    320
#define HW    (Hh*Ww)          // 76800
#define NUM   8
#define C_FEA 8
#define COUT  24
#define HIN   120
#define WIN   160
#define QW    (HW/8)           // 9600

// Scratch (device globals; no runtime allocation allowed)
__device__ __align__(16) float g_oaT[(size_t)Bq*HW*COUT];      // conv output, pixel-major (29.5 MB)
__device__ __align__(16) float g_feaT[(size_t)Bq*HW*C_FEA];    // upsampled fea, channel-last (9.8 MB)
__device__ __align__(16) float g_cw[(size_t)Bq*HW*NUM];        // cos_w, pixel-major (9.8 MB)

#define FFMA2(d,a,b,c_) asm("fma.rn.f32x2 %0, %1, %2, %3;" : "=l"(d) : "l"(a), "l"(b), "l"(c_))
#define DUP2(d,s)       asm("mov.b64 %0, {%1, %1};" : "=l"(d) : "f"(s))

// ---------------------------------------------------------------------------
// Stage 1: 2x bilinear upsample (jax.image.resize "bilinear": half-pixel
// centers -> weights {0.75,0.25}, edge renorm == index clamp).
// Output channel-last: g_feaT[b][i][j][c].
// ---------------------------------------------------------------------------
__global__ void upsample_kernel(const float* __restrict__ fea) {
    int t = blockIdx.x * 256 + threadIdx.x;
    if (t >= Bq * HW) return;
    int b = t / HW; int pix = t - b * HW;
    int i = pix / Ww; int j = pix - i * Ww;

    int ky = i >> 1;
    int y1 = (i & 1) ? min(ky + 1, HIN - 1) : max(ky - 1, 0);
    int kx = j >> 1;
    int x1 = (j & 1) ? min(kx + 1, WIN - 1) : max(kx - 1, 0);
    const float wm = 0.75f, ws = 0.25f;

    float* dst = &g_feaT[(size_t)t * C_FEA];
#pragma unroll
    for (int c = 0; c < C_FEA; c++) {
        const float* fp = fea + ((size_t)(b * C_FEA + c)) * (HIN * WIN);
        float v00 = fp[ky * WIN + kx];
        float v01 = fp[ky * WIN + x1];
        float v10 = fp[y1 * WIN + kx];
        float v11 = fp[y1 * WIN + x1];
        dst[c] = wm * (wm * v00 + ws * v01) + ws * (wm * v10 + ws * v11);
    }
}

// ---------------------------------------------------------------------------
// Stage 2: 3x3 conv, 64 -> 24 channels, pad 1, + bias. FFMA2, each thread
// computes TWO horizontally adjacent pixels so the 6 LDS.128 weight loads
// per (c,k) feed 24 FFMA2 (was 12). 128-thread blocks, 8x32 pixel tile.
// Output written pixel-major.
// ---------------------------------------------------------------------------
__global__ __launch_bounds__(128) void conv_kernel(const float* __restrict__ gin,
                                                   const float* __restrict__ wgt,
                                                   const float* __restrict__ bias) {
    __shared__ __align__(16) float sg[16 * 10 * 34];   // 16ch x (8+2) x (32+2)
    __shared__ __align__(16) float sw[16 * 9 * 24];    // [c][k][o]

    int tx = threadIdx.x & 15, ty = threadIdx.x >> 4;  // tx: pixel pair, ty: row
    int bx = blockIdx.x * 32, by = blockIdx.y * 8, b = blockIdx.z;

    unsigned long long accA[12], accB[12];
#pragma unroll
    for (int h = 0; h < 12; h++) {
        float b0 = bias[2 * h], b1 = bias[2 * h + 1];
        unsigned long long bb;
        asm("mov.b64 %0, {%1, %2};" : "=l"(bb) : "f"(b0), "f"(b1));
        accA[h] = bb; accB[h] = bb;
    }

    for (int cc = 0; cc < 4; cc++) {
        __syncthreads();
        // load guidance tile (with zero pad halo)
        for (int idx = threadIdx.x; idx < 16 * 340; idx += 128) {
            int c = idx / 340; int r = idx - c * 340;
            int yy = r / 34;   int xx = r - yy * 34;
            int gy = by + yy - 1, gx = bx + xx - 1;
            float v = 0.f;
            if (gy >= 0 && gy < Hh && gx >= 0 && gx < Ww)
                v = gin[((size_t)(b * CH_G + cc * 16 + c)) * HW + gy * Ww + gx];
            sg[idx] = v;
        }
        // load weight chunk, layout [c][k][o]
        for (int idx = threadIdx.x; idx < 16 * 216; idx += 128) {
            int c = idx / 216; int r = idx - c * 216;
            int k = r / 24;    int o = r - k * 24;
            sw[idx] = wgt[((size_t)o * CH_G + cc * 16 + c) * 9 + k];
        }
        __syncthreads();

        for (int c = 0; c < 16; c++) {
            // taps for pixel pair (2tx, 2tx+1): 3 rows x 4 cols
            unsigned long long gd[12];
#pragma unroll
            for (int dy = 0; dy < 3; dy++)
#pragma unroll
                for (int dx = 0; dx < 4; dx++) {
                    float gv = sg[c * 340 + (ty + dy) * 34 + (2 * tx + dx)];
                    DUP2(gd[dy * 4 + dx], gv);
                }
#pragma unroll
            for (int dy = 0; dy < 3; dy++)
#pragma unroll
                for (int kx = 0; kx < 3; kx++) {
                    const ulonglong2* wv = (const ulonglong2*)&sw[(c * 9 + dy * 3 + kx) * 24];
                    unsigned long long gk0 = gd[dy * 4 + kx];
                    unsigned long long gk1 = gd[dy * 4 + kx + 1];
#pragma unroll
                    for (int h = 0; h < 6; h++) {
                        ulonglong2 w2 = wv[h];
                        FFMA2(accA[2 * h],     w2.x, gk0, accA[2 * h]);
                        FFMA2(accA[2 * h + 1], w2.y, gk0, accA[2 * h + 1]);
                        FFMA2(accB[2 * h],     w2.x, gk1, accB[2 * h]);
                        FFMA2(accB[2 * h + 1], w2.y, gk1, accB[2 * h + 1]);
                    }
                }
        }
    }

    int gy = by + ty, gx = bx + 2 * tx;
    size_t pix = (size_t)gy * Ww + gx;
    ulonglong2* dstA = (ulonglong2*)&g_oaT[((size_t)b * HW + pix) * COUT];
    ulonglong2* dstB = (ulonglong2*)&g_oaT[((size_t)b * HW + pix + 1) * COUT];
#pragma unroll
    for (int h = 0; h < 6; h++) {
        dstA[h] = make_ulonglong2(accA[2 * h], accA[2 * h + 1]);
        dstB[h] = make_ulonglong2(accB[2 * h], accB[2 * h + 1]);
    }
}

// ---------------------------------------------------------------------------
// Stage 3: fused deformable-sample + scramble-reduce, shuffle version.
// Thread (b,q,a) owns sample pixel pix2 = 8q+a. It bilinear-samples ALL 8
// fea channels per (n) point with vectorized float4 loads, multiplies by the
// coalesced weights fw[ch] = feaT[b][ch*QW+q][a], and an 8-lane butterfly
// produces cw[b][ch*QW+q][n] = sum_a fw*s; lane a writes channel ch = a.
// ---------------------------------------------------------------------------
__global__ __launch_bounds__(256) void cw_kernel() {
    int t = blockIdx.x * 256 + threadIdx.x;   // grid exact: Bq*QW*8 threads
    int a = t & 7; int qg = t >> 3;
    int b = qg / QW; int q = qg - b * QW;
    int pix2 = q * 8 + a;
    int i2 = pix2 / Ww; int j2 = pix2 - i2 * Ww;
    const float* fT = g_feaT + (size_t)b * HW * C_FEA;

    // 16 offset floats for pix2 (coalesced across the 8-lane group)
    float of[16];
    {
        const float4* op = (const float4*)(g_oaT + ((size_t)b * HW + pix2) * COUT);
        float4 o0 = op[0], o1 = op[1], o2 = op[2], o3 = op[3];
        of[0] = o0.x; of[1] = o0.y; of[2]  = o0.z; of[3]  = o0.w;
        of[4] = o1.x; of[5] = o1.y; of[6]  = o1.z; of[7]  = o1.w;
        of[8] = o2.x; of[9] = o2.y; of[10] = o2.z; of[11] = o2.w;
        of[12] = o3.x; of[13] = o3.y; of[14] = o3.z; of[15] = o3.w;
    }

    // fw[ch] = feaT[b][ch*QW+q][a]  (fully coalesced per ch across the warp)
    float fw[8];
#pragma unroll
    for (int ch = 0; ch < 8; ch++)
        fw[ch] = fT[((size_t)(ch * QW + q)) * C_FEA + a];

    float fi2 = (float)i2, fj2 = (float)j2;

#pragma unroll
    for (int n = 0; n < 8; n++) {
        float base = (n < 4) ? fi2 : fj2;
        float x = of[2 * n] + base;
        float y = of[2 * n + 1] + base;

        float x0 = floorf(x), y0 = floorf(y);
        float fx = x - x0, fy = y - y0;

        float4 s0 = make_float4(0.f, 0.f, 0.f, 0.f);
        float4 s1 = make_float4(0.f, 0.f, 0.f, 0.f);
#pragma unroll
        for (int cy = 0; cy < 2; cy++)
#pragma unroll
            for (int cx = 0; cx < 2; cx++) {
                float xi = x0 + cx, yi = y0 + cy;
                if (xi >= 0.f && xi <= (float)(Ww - 1) && yi >= 0.f && yi <= (float)(Hh - 1)) {
                    float wb = (cy ? fy : 1.f - fy) * (cx ? fx : 1.f - fx);
                    const float4* v = (const float4*)(fT + ((size_t)((int)yi * Ww + (int)xi)) * C_FEA);
                    float4 v0 = v[0], v1 = v[1];
                    s0.x += wb * v0.x; s0.y += wb * v0.y; s0.z += wb * v0.z; s0.w += wb * v0.w;
                    s1.x += wb * v1.x; s1.y += wb * v1.y; s1.z += wb * v1.z; s1.w += wb * v1.w;
                }
            }

        float prt[8];
        prt[0] = fw[0] * s0.x; prt[1] = fw[1] * s0.y;
        prt[2] = fw[2] * s0.z; prt[3] = fw[3] * s0.w;
        prt[4] = fw[4] * s1.x; prt[5] = fw[5] * s1.y;
        prt[6] = fw[6] * s1.z; prt[7] = fw[7] * s1.w;

        // butterfly sum over the 8-lane a-group (xor offsets stay in-group)
#pragma unroll
        for (int ofs = 1; ofs < 8; ofs <<= 1)
#pragma unroll
            for (int ch = 0; ch < 8; ch++)
                prt[ch] += __shfl_xor_sync(0xffffffffu, prt[ch], ofs);

        // lane a writes channel ch = a
        float outv = prt[0];
#pragma unroll
        for (int ch = 1; ch < 8; ch++)
            if (a == ch) outv = prt[ch];
        g_cw[((size_t)b * HW + (size_t)a * QW + q) * NUM + n] = outv;
    }
}

// single-channel bilinear with zero padding (reference _bilinear_zeros)
__device__ __forceinline__ float bil1(const float* __restrict__ img, float x, float y) {
    float x0 = floorf(x), y0 = floorf(y);
    float fx = x - x0, fy = y - y0;
    float r = 0.f;
#pragma unroll
    for (int cy = 0; cy < 2; cy++) {
#pragma unroll
        for (int cx = 0; cx < 2; cx++) {
            float xi = x0 + cx, yi = y0 + cy;
            if (xi >= 0.f && xi <= (float)(Ww - 1) && yi >= 0.f && yi <= (float)(Hh - 1)) {
                float wgt = (cy ? fy : 1.f - fy) * (cx ? fx : 1.f - fx);
                r += wgt * img[(int)yi * Ww + (int)xi];
            }
        }
    }
    return r;
}

// ---------------------------------------------------------------------------
// Stage 4: epilogue. Reads oaT (6 x LDG.128) and cw (2 x LDG.128); TGASS
// tanh scaling, confidence bilinear on gt_depth_conf, abs-sum clamp
// normalize, reference channel insert, softmax, write both outputs.
// ---------------------------------------------------------------------------
__global__ void final_kernel(const float* __restrict__ gt,
                             const float* __restrict__ ascp,
                             float* __restrict__ out) {
    int t = blockIdx.x * 256 + threadIdx.x;
    if (t >= Bq * HW) return;
    int b = t / HW; int pix = t - b * HW;
    int i = pix / Ww; int j = pix - i * Ww;

    float o[COUT];
    {
        const float4* ov = (const float4*)&g_oaT[(size_t)t * COUT];
#pragma unroll
        for (int h = 0; h < 6; h++) {
            float4 v = ov[h];
            o[4 * h + 0] = v.x; o[4 * h + 1] = v.y;
            o[4 * h + 2] = v.z; o[4 * h + 3] = v.w;
        }
    }
    float cosw[8];
    {
        const float4* cv = (const float4*)&g_cw[(size_t)t * NUM];
        float4 c0 = cv[0], c1 = cv[1];
        cosw[0] = c0.x; cosw[1] = c0.y; cosw[2] = c0.z; cosw[3] = c0.w;
        cosw[4] = c1.x; cosw[5] = c1.y; cosw[6] = c1.z; cosw[7] = c1.w;
    }

    float denom = ascp[0] + 1e-8f;
    const float* gb = gt + (size_t)b * HW;

    float aff[8];
#pragma unroll
    for (int n = 0; n < 8; n++) {
        float a0 = tanhf(o[16 + n] * cosw[n]) / denom;
        float y = o[2 * n]     + (float)i;   // channel 0 = dy
        float x = o[2 * n + 1] + (float)j;   // channel 1 = dx
        aff[n] = a0 * bil1(gb, x, y);
    }

    float sabs = 0.f;
#pragma unroll
    for (int n = 0; n < 8; n++) sabs += fabsf(aff[n]);
    sabs += 1e-4f;
    sabs = fmaxf(sabs, 1.0f);

    float ssum = 0.f;
#pragma unroll
    for (int n = 0; n < 8; n++) { aff[n] = aff[n] / sabs; ssum += aff[n]; }

    float v[9];
    v[0] = aff[0]; v[1] = aff[1]; v[2] = aff[2]; v[3] = aff[3];
    v[4] = 1.0f - ssum;
    v[5] = aff[4]; v[6] = aff[5]; v[7] = aff[6]; v[8] = aff[7];

    float m = v[0];
#pragma unroll
    for (int k = 1; k < 9; k++) m = fmaxf(m, v[k]);
    float e[9], es = 0.f;
#pragma unroll
    for (int k = 0; k < 9; k++) { e[k] = expf(v[k] - m); es += e[k]; }
    float inv = 1.0f / es;

    // output: offset_full (B,18,H,W) flattened, then aff_full (B,9,H,W)
    const size_t OFFA = (size_t)Bq * 18 * HW;
#pragma unroll
    for (int k = 0; k < 8; k++)
        out[((size_t)(b * 18 + k)) * HW + pix] = o[k];
    out[((size_t)(b * 18 + 8)) * HW + pix] = 0.f;
    out[((size_t)(b * 18 + 9)) * HW + pix] = 0.f;
#pragma unroll
    for (int k = 10; k < 18; k++)
        out[((size_t)(b * 18 + k)) * HW + pix] = o[k - 2];
#pragma unroll
    for (int k = 0; k < 9; k++)
        out[OFFA + ((size_t)(b * 9 + k)) * HW + pix] = e[k] * inv;
}

// ---------------------------------------------------------------------------
extern "C" void kernel_launch(void* const* d_in, const int* in_sizes, int n_in,
                              void* d_out, int out_size) {
    const float* guidance = (const float*)d_in[0];
    const float* gt       = (const float*)d_in[1];
    const float* fea      = (const float*)d_in[2];
    const float* conv_w   = (const float*)d_in[3];
    const float* conv_b   = (const float*)d_in[4];
    const float* asc      = (const float*)d_in[5];
    float* out = (float*)d_out;

    upsample_kernel<<<(Bq * HW + 255) / 256, 256>>>(fea);

    dim3 cg(Ww / 32, Hh / 8, Bq);   // 10 x 30 x 4 = 1200 blocks, 128 threads
    conv_kernel<<<cg, 128>>>(guidance, conv_w, conv_b);

    cw_kernel<<<(Bq * QW * 8) / 256, 256>>>();   // 1200 blocks exact

    final_kernel<<<(Bq * HW + 255) / 256, 256>>>(gt, asc, out);
}

// round 6
// speedup vs baseline: 1.2064x; 1.2064x over previous
#include <cuda_runtime.h>
#include <cuda_bf16.h>
#include <math.h>

// Problem constants
#define Bq    4
#define CH_G  64
#define Hh    240
#define Ww    320
#define HW    (Hh*Ww)          // 76800
#define NUM   8
#define C_FEA 8
#define COUT  24
#define HIN   120
#define WIN   160
#define Pn    (HW*NUM)         // 614400

// Scratch (device globals; no runtime allocation allowed)
__device__ __align__(16) float g_oaT[(size_t)Bq*HW*COUT];      // conv output, pixel-major (29.5 MB)
__device__ __align__(16) float g_feaT[(size_t)Bq*HW*C_FEA];    // upsampled fea, channel-last (9.8 MB)
__device__ __align__(16) float g_smp[(size_t)Bq*C_FEA*Pn];     // sampled tensor (78.6 MB)

#define FFMA2(d,a,b,c_) asm("fma.rn.f32x2 %0, %1, %2, %3;" : "=l"(d) : "l"(a), "l"(b), "l"(c_))
#define DUP2(d,s)       asm("mov.b64 %0, {%1, %1};" : "=l"(d) : "f"(s))

// ---------------------------------------------------------------------------
// Stage 1: 2x bilinear upsample (jax.image.resize "bilinear": half-pixel
// centers -> weights {0.75,0.25}, edge renorm == index clamp).
// Output channel-last: g_feaT[b][i][j][c].
// ---------------------------------------------------------------------------
__global__ void upsample_kernel(const float* __restrict__ fea) {
    int t = blockIdx.x * 256 + threadIdx.x;
    if (t >= Bq * HW) return;
    int b = t / HW; int pix = t - b * HW;
    int i = pix / Ww; int j = pix - i * Ww;

    int ky = i >> 1;
    int y1 = (i & 1) ? min(ky + 1, HIN - 1) : max(ky - 1, 0);
    int kx = j >> 1;
    int x1 = (j & 1) ? min(kx + 1, WIN - 1) : max(kx - 1, 0);
    const float wm = 0.75f, ws = 0.25f;

    float* dst = &g_feaT[(size_t)t * C_FEA];
#pragma unroll
    for (int c = 0; c < C_FEA; c++) {
        const float* fp = fea + ((size_t)(b * C_FEA + c)) * (HIN * WIN);
        float v00 = fp[ky * WIN + kx];
        float v01 = fp[ky * WIN + x1];
        float v10 = fp[y1 * WIN + kx];
        float v11 = fp[y1 * WIN + x1];
        dst[c] = wm * (wm * v00 + ws * v01) + ws * (wm * v10 + ws * v11);
    }
}

// ---------------------------------------------------------------------------
// Stage 2: 3x3 conv, 64 -> 24 channels, pad 1, + bias. FFMA2 (fma.rn.f32x2)
// with output channels paired: 12 f32x2 accumulators. One pixel per thread,
// 256-thread blocks (proven R4 configuration). Output pixel-major.
// ---------------------------------------------------------------------------
__global__ __launch_bounds__(256) void conv_kernel(const float* __restrict__ gin,
                                                   const float* __restrict__ wgt,
                                                   const float* __restrict__ bias) {
    __shared__ __align__(16) float sg[16 * 10 * 34];   // 16ch x (8+2) x (32+2)
    __shared__ __align__(16) float sw[16 * 9 * 24];    // [c][k][o]

    int tx = threadIdx.x & 31, ty = threadIdx.x >> 5;
    int bx = blockIdx.x * 32, by = blockIdx.y * 8, b = blockIdx.z;

    unsigned long long acc[12];
#pragma unroll
    for (int q = 0; q < 12; q++) {
        float b0 = bias[2 * q], b1 = bias[2 * q + 1];
        asm("mov.b64 %0, {%1, %2};" : "=l"(acc[q]) : "f"(b0), "f"(b1));
    }

    for (int cc = 0; cc < 4; cc++) {
        __syncthreads();
        // load guidance tile (with zero pad halo)
        for (int idx = threadIdx.x; idx < 16 * 340; idx += 256) {
            int c = idx / 340; int r = idx - c * 340;
            int yy = r / 34;   int xx = r - yy * 34;
            int gy = by + yy - 1, gx = bx + xx - 1;
            float v = 0.f;
            if (gy >= 0 && gy < Hh && gx >= 0 && gx < Ww)
                v = gin[((size_t)(b * CH_G + cc * 16 + c)) * HW + gy * Ww + gx];
            sg[idx] = v;
        }
        // load weight chunk, layout [c][k][o]
        for (int idx = threadIdx.x; idx < 16 * 216; idx += 256) {
            int c = idx / 216; int r = idx - c * 216;
            int k = r / 24;    int o = r - k * 24;
            sw[idx] = wgt[((size_t)o * CH_G + cc * 16 + c) * 9 + k];
        }
        __syncthreads();

        for (int c = 0; c < 16; c++) {
            unsigned long long gd[9];
#pragma unroll
            for (int dy = 0; dy < 3; dy++)
#pragma unroll
                for (int dx = 0; dx < 3; dx++) {
                    float gv = sg[c * 340 + (ty + dy) * 34 + (tx + dx)];
                    DUP2(gd[dy * 3 + dx], gv);
                }
#pragma unroll
            for (int k = 0; k < 9; k++) {
                const ulonglong2* wv = (const ulonglong2*)&sw[(c * 9 + k) * 24];
                unsigned long long gk = gd[k];
#pragma unroll
                for (int h = 0; h < 6; h++) {
                    ulonglong2 w2 = wv[h];
                    FFMA2(acc[2 * h],     w2.x, gk, acc[2 * h]);
                    FFMA2(acc[2 * h + 1], w2.y, gk, acc[2 * h + 1]);
                }
            }
        }
    }

    int gy = by + ty, gx = bx + tx;
    size_t pix = (size_t)gy * Ww + gx;
    ulonglong2* dst = (ulonglong2*)&g_oaT[((size_t)b * HW + pix) * COUT];
#pragma unroll
    for (int h = 0; h < 6; h++)
        dst[h] = make_ulonglong2(acc[2 * h], acc[2 * h + 1]);
}

// ---------------------------------------------------------------------------
// Stage 3: deformable sampling of fea_up (8 channels per sample point).
// For offset index n at sample pixel pix: x = oa[2n]+base, y = oa[2n+1]+base,
// base = i (row) for n<4 else j (col). Bilinear with zero padding.
// Vectorized float4 tap loads; coalesced channel-major stores g_smp[b][c][p],
// p = pix*8 + n.  (Proven R2 structure; offsets now read pixel-major.)
// ---------------------------------------------------------------------------
__global__ void sample_kernel() {
    int t = blockIdx.x * 256 + threadIdx.x;
    if (t >= Bq * Pn) return;
    int b = t / Pn; int p = t - b * Pn;
    int pix = p >> 3; int n = p & 7;
    int i = pix / Ww; int j = pix - i * Ww;

    float2 of = *(const float2*)(g_oaT + ((size_t)b * HW + pix) * COUT + 2 * n);
    float base = (n < 4) ? (float)i : (float)j;
    float x = of.x + base;
    float y = of.y + base;

    float x0 = floorf(x), y0 = floorf(y);
    float fx = x - x0, fy = y - y0;

    float acc0 = 0, acc1 = 0, acc2 = 0, acc3 = 0, acc4 = 0, acc5 = 0, acc6 = 0, acc7 = 0;
    const float* fb = g_feaT + (size_t)b * HW * C_FEA;
#pragma unroll
    for (int cy = 0; cy < 2; cy++) {
#pragma unroll
        for (int cx = 0; cx < 2; cx++) {
            float xi = x0 + cx, yi = y0 + cy;
            float wgt = (cy ? fy : 1.f - fy) * (cx ? fx : 1.f - fx);
            if (xi >= 0.f && xi <= (float)(Ww - 1) && yi >= 0.f && yi <= (float)(Hh - 1)) {
                int xc = (int)xi, yc = (int)yi;
                const float4* v = (const float4*)(fb + ((size_t)yc * Ww + xc) * C_FEA);
                float4 v0 = v[0], v1 = v[1];
                acc0 += wgt * v0.x; acc1 += wgt * v0.y; acc2 += wgt * v0.z; acc3 += wgt * v0.w;
                acc4 += wgt * v1.x; acc5 += wgt * v1.y; acc6 += wgt * v1.z; acc7 += wgt * v1.w;
            }
        }
    }
    float* sb = g_smp + (size_t)b * C_FEA * Pn;
    sb[(size_t)0 * Pn + p] = acc0;
    sb[(size_t)1 * Pn + p] = acc1;
    sb[(size_t)2 * Pn + p] = acc2;
    sb[(size_t)3 * Pn + p] = acc3;
    sb[(size_t)4 * Pn + p] = acc4;
    sb[(size_t)5 * Pn + p] = acc5;
    sb[(size_t)6 * Pn + p] = acc6;
    sb[(size_t)7 * Pn + p] = acc7;
}

// single-channel bilinear with zero padding (reference _bilinear_zeros)
__device__ __forceinline__ float bil1(const float* __restrict__ img, float x, float y) {
    float x0 = floorf(x), y0 = floorf(y);
    float fx = x - x0, fy = y - y0;
    float r = 0.f;
#pragma unroll
    for (int cy = 0; cy < 2; cy++) {
#pragma unroll
        for (int cx = 0; cx < 2; cx++) {
            float xi = x0 + cx, yi = y0 + cy;
            if (xi >= 0.f && xi <= (float)(Ww - 1) && yi >= 0.f && yi <= (float)(Hh - 1)) {
                float wgt = (cy ? fy : 1.f - fy) * (cx ? fx : 1.f - fx);
                r += wgt * img[(int)yi * Ww + (int)xi];
            }
        }
    }
    return r;
}

// ---------------------------------------------------------------------------
// Stage 4: fused epilogue (proven R2 structure). Scramble-gather:
// cos_w[c](pix) = sum_a fea[a] * g_smp[b][Q/76800][(Q%76800)*8 + c], Q=pix*8+a
// (8 consecutive floats per gather -> 2x LDG.128). Then TGASS tanh scaling,
// confidence bilinear on gt_depth_conf, abs-sum clamp normalize, reference
// channel insert, softmax, write both outputs.
// ---------------------------------------------------------------------------
__global__ void final_kernel(const float* __restrict__ gt,
                             const float* __restrict__ ascp,
                             float* __restrict__ out) {
    int t = blockIdx.x * 256 + threadIdx.x;
    if (t >= Bq * HW) return;
    int b = t / HW; int pix = t - b * HW;
    int i = pix / Ww; int j = pix - i * Ww;

    float o[COUT];
    {
        const float4* ov = (const float4*)&g_oaT[(size_t)t * COUT];
#pragma unroll
        for (int h = 0; h < 6; h++) {
            float4 v = ov[h];
            o[4 * h + 0] = v.x; o[4 * h + 1] = v.y;
            o[4 * h + 2] = v.z; o[4 * h + 3] = v.w;
        }
    }

    const float4* fv = (const float4*)&g_feaT[(size_t)t * C_FEA];
    float4 f0 = fv[0], f1 = fv[1];
    float fea[8] = {f0.x, f0.y, f0.z, f0.w, f1.x, f1.y, f1.z, f1.w};

    float cw0 = 0, cw1 = 0, cw2 = 0, cw3 = 0, cw4 = 0, cw5 = 0, cw6 = 0, cw7 = 0;
#pragma unroll
    for (int a = 0; a < 8; a++) {
        int Q  = pix * 8 + a;
        int ch = Q / HW;
        int p2 = Q - ch * HW;
        const float4* sp = (const float4*)&g_smp[((size_t)(b * C_FEA + ch)) * Pn + (size_t)p2 * 8];
        float4 s0 = sp[0], s1 = sp[1];
        float fa = fea[a];
        cw0 += fa * s0.x; cw1 += fa * s0.y; cw2 += fa * s0.z; cw3 += fa * s0.w;
        cw4 += fa * s1.x; cw5 += fa * s1.y; cw6 += fa * s1.z; cw7 += fa * s1.w;
    }
    float cosw[8] = {cw0, cw1, cw2, cw3, cw4, cw5, cw6, cw7};

    float denom = ascp[0] + 1e-8f;
    const float* gb = gt + (size_t)b * HW;

    float aff[8];
#pragma unroll
    for (int n = 0; n < 8; n++) {
        float a0 = tanhf(o[16 + n] * cosw[n]) / denom;
        float y = o[2 * n]     + (float)i;   // channel 0 = dy
        float x = o[2 * n + 1] + (float)j;   // channel 1 = dx
        aff[n] = a0 * bil1(gb, x, y);
    }

    float sabs = 0.f;
#pragma unroll
    for (int n = 0; n < 8; n++) sabs += fabsf(aff[n]);
    sabs += 1e-4f;
    sabs = fmaxf(sabs, 1.0f);

    float ssum = 0.f;
#pragma unroll
    for (int n = 0; n < 8; n++) { aff[n] = aff[n] / sabs; ssum += aff[n]; }

    float v[9];
    v[0] = aff[0]; v[1] = aff[1]; v[2] = aff[2]; v[3] = aff[3];
    v[4] = 1.0f - ssum;
    v[5] = aff[4]; v[6] = aff[5]; v[7] = aff[6]; v[8] = aff[7];

    float m = v[0];
#pragma unroll
    for (int k = 1; k < 9; k++) m = fmaxf(m, v[k]);
    float e[9], es = 0.f;
#pragma unroll
    for (int k = 0; k < 9; k++) { e[k] = expf(v[k] - m); es += e[k]; }
    float inv = 1.0f / es;

    // output: offset_full (B,18,H,W) flattened, then aff_full (B,9,H,W)
    const size_t OFFA = (size_t)Bq * 18 * HW;
#pragma unroll
    for (int k = 0; k < 8; k++)
        out[((size_t)(b * 18 + k)) * HW + pix] = o[k];
    out[((size_t)(b * 18 + 8)) * HW + pix] = 0.f;
    out[((size_t)(b * 18 + 9)) * HW + pix] = 0.f;
#pragma unroll
    for (int k = 10; k < 18; k++)
        out[((size_t)(b * 18 + k)) * HW + pix] = o[k - 2];
#pragma unroll
    for (int k = 0; k < 9; k++)
        out[OFFA + ((size_t)(b * 9 + k)) * HW + pix] = e[k] * inv;
}

// ---------------------------------------------------------------------------
extern "C" void kernel_launch(void* const* d_in, const int* in_sizes, int n_in,
                              void* d_out, int out_size) {
    const float* guidance = (const float*)d_in[0];
    const float* gt       = (const float*)d_in[1];
    const float* fea      = (const float*)d_in[2];
    const float* conv_w   = (const float*)d_in[3];
    const float* conv_b   = (const float*)d_in[4];
    const float* asc      = (const float*)d_in[5];
    float* out = (float*)d_out;

    upsample_kernel<<<(Bq * HW + 255) / 256, 256>>>(fea);

    dim3 cg(Ww / 32, Hh / 8, Bq);   // 10 x 30 x 4 = 1200 blocks, 256 threads
    conv_kernel<<<cg, 256>>>(guidance, conv_w, conv_b);

    sample_kernel<<<(Bq * Pn + 255) / 256, 256>>>();

    final_kernel<<<(Bq * HW + 255) / 256, 256>>>(gt, asc, out);
}